// round 15
// baseline (speedup 1.0000x reference)
#include <cuda_runtime.h>
#include <cuda_bf16.h>

// FQCNN_layer: closed-form evaluation. FINAL (frozen at hardware floor).
//
// Math: expval(Z on wire 4) is invariant under the post-encoding circuit
// (H on wire 5, controlled-U3s on wire 6: unitaries on wires != 4 preserve
// the wire-4 marginal; controls never mix control-wire amplitudes). Summing
// the 16 equal-weight H^{x4} branches of the commuting (controlled-)RYs on
// wire 4, then sum-to-product (all identities exact):
//   <Z> = 0.5 c(A) + 0.25 c(d) c(A+m) + 0.125 [c(d) + c(m)] c(A+m+w)
// where (A,u,v,w) = (im[j,k], im[j,k+1], im[j+1,k], im[j+1,k+1]),
//       m = (u+v)/2, d = (u-v)/2,  using cos(u/2)cos(v/2) = [c(d)+c(m)]/2.
// 5 MUFU.COS per patch (down from a 128-dim complex statevector sim).
// U3_w is provably unused.
//
// Perf: 8 configurations measured (occ 30-68%, grids 296-1536, blocks
// 128-512, 5-7 cos, MLP 1-2, 1-2 out/thread) all land at 4.77-4.86us
// device time: the kernel is pinned at the launch/ramp + single cold-DRAM
// pass floor with every pipe <9% utilized. 3.9 MB mandatory traffic on a
// ~5000-cycle-ramp chip is launch-overhead-bound at this size; no
// structural lever remains under the single-graph-launch contract.
//
// Index collapse: i = bc*4096 + oh*64 + ow (output, float units)
//                 base = bc*8192 + oh*128 + ow = 2*i - (i & 63) (float2 units)

#define N_OUT 196608   // 16*3*64*64 == 384 * 512 exactly

__global__ __launch_bounds__(512) void fqcnn_kernel(const float2* __restrict__ in2,
                                                    float* __restrict__ out) {
    int i = blockIdx.x * blockDim.x + threadIdx.x;   // exact grid, no tail

    int base = 2 * i - (i & 63);        // float2 index of (A,u) pair
    const float2 r0 = in2[base];        // row 2*oh   : A u
    const float2 r1 = in2[base + 64];   // row 2*oh+1 : v w

    float A = r0.x, u = r0.y, v = r1.x, w = r1.y;

    float hu = 0.5f * u;
    float hv = 0.5f * v;
    float m  = hu + hv;
    float d  = hu - hv;

    float cA = __cosf(A);
    float cd = __cosf(d);
    float cm = __cosf(m);
    float c1 = __cosf(A + m);
    float c2 = __cosf(A + m + w);

    out[i] = 0.5f * cA + 0.25f * cd * c1 + 0.125f * (cd + cm) * c2;
}

extern "C" void kernel_launch(void* const* d_in, const int* in_sizes, int n_in,
                              void* d_out, int out_size) {
    const float2* x  = (const float2*)d_in[0];   // [16,3,128,128] fp32
    // d_in[1] = U3_w — unused (see math above)
    float* out = (float*)d_out;                  // [16,3,64,64] fp32

    fqcnn_kernel<<<N_OUT / 512, 512>>>(x, out);
}

// round 16
// speedup vs baseline: 1.0667x; 1.0667x over previous
#include <cuda_runtime.h>
#include <cuda_bf16.h>

// FQCNN_layer: closed-form evaluation. FINAL (frozen at hardware floor).
//
// Math: expval(Z on wire 4) is invariant under the post-encoding circuit
// (H on wire 5, controlled-U3s on wire 6: unitaries on wires != 4 preserve
// the wire-4 marginal; controls never mix control-wire amplitudes). Summing
// the 16 equal-weight H^{x4} branches of the commuting (controlled-)RYs on
// wire 4, then sum-to-product (all identities exact):
//   <Z> = 0.5 c(A) + 0.25 c(d) c(A+m) + 0.125 [c(d) + c(m)] c(A+m+w)
// where (A,u,v,w) = (im[j,k], im[j,k+1], im[j+1,k], im[j+1,k+1]),
//       m = (u+v)/2, d = (u-v)/2,  using cos(u/2)cos(v/2) = [c(d)+c(m)]/2.
// 5 MUFU.COS per patch (down from a 128-dim complex statevector sim).
// U3_w is provably unused.
//
// Perf: 9 measurements across every config axis (occ 30-68%, grids
// 296-1536, blocks 128-512, 5-7 cos, MLP 1-2, 1-2 out/thread) land in
// 4.54-4.86us device time, and the IDENTICAL source measured 4.83 (R13)
// then 4.54 (R15): run-to-run noise (~±0.3us) exceeds every remaining
// candidate delta. The kernel is pinned at the launch/ramp + single
// cold-DRAM-pass floor with every pipe <9% utilized. Frozen.
//
// Index collapse: i = bc*4096 + oh*64 + ow (output, float units)
//                 base = bc*8192 + oh*128 + ow = 2*i - (i & 63) (float2 units)

#define N_OUT 196608   // 16*3*64*64 == 384 * 512 exactly

__global__ __launch_bounds__(512) void fqcnn_kernel(const float2* __restrict__ in2,
                                                    float* __restrict__ out) {
    int i = blockIdx.x * blockDim.x + threadIdx.x;   // exact grid, no tail

    int base = 2 * i - (i & 63);        // float2 index of (A,u) pair
    const float2 r0 = in2[base];        // row 2*oh   : A u
    const float2 r1 = in2[base + 64];   // row 2*oh+1 : v w

    float A = r0.x, u = r0.y, v = r1.x, w = r1.y;

    float hu = 0.5f * u;
    float hv = 0.5f * v;
    float m  = hu + hv;
    float d  = hu - hv;

    float cA = __cosf(A);
    float cd = __cosf(d);
    float cm = __cosf(m);
    float c1 = __cosf(A + m);
    float c2 = __cosf(A + m + w);

    out[i] = 0.5f * cA + 0.25f * cd * c1 + 0.125f * (cd + cm) * c2;
}

extern "C" void kernel_launch(void* const* d_in, const int* in_sizes, int n_in,
                              void* d_out, int out_size) {
    const float2* x  = (const float2*)d_in[0];   // [16,3,128,128] fp32
    // d_in[1] = U3_w — unused (see math above)
    float* out = (float*)d_out;                  // [16,3,64,64] fp32

    fqcnn_kernel<<<N_OUT / 512, 512>>>(x, out);
}